// round 3
// baseline (speedup 1.0000x reference)
#include <cuda_runtime.h>
#include <cuda_fp16.h>
#include <cstdint>

// Problem constants
#define KW    8
#define BB    16
#define LL    2048
#define DD    128
#define LP    (LL + 7)      // padded rows per batch (7 zero-pad windows)
#define GD    384           // 3*D gate dim
#define NCTA  256           // 256 tiles of 128 rows

#define HS    136           // SMEM row stride in halves (272B -> conflict-free ldmatrix)
#define HT_BYTES   (128 * HS * 2)              // 34816: h (or x) tile
#define SMEM_BYTES (HT_BYTES + GD * HS * 2)    // + 104448 = 139264

// fp32 scratch: xproj[b, lp, g] = x@W_ih^T + b_ih (+ b_hh for r,z); pad rows = bias only
__device__ float g_xproj[BB * LP * GD];

// ---------------- helpers ----------------
static __device__ __forceinline__ uint32_t smem_u32(const void* p) {
    uint32_t a;
    asm("{ .reg .u64 t; cvta.to.shared.u64 t, %1; cvt.u32.u64 %0, t; }" : "=r"(a) : "l"(p));
    return a;
}
static __device__ __forceinline__ float ex2f(float x) { float y; asm("ex2.approx.f32 %0,%1;" : "=f"(y) : "f"(x)); return y; }
static __device__ __forceinline__ float rcpf(float x) { float y; asm("rcp.approx.f32 %0,%1;" : "=f"(y) : "f"(x)); return y; }
static __device__ __forceinline__ float sigf(float x)   { return rcpf(1.f + ex2f(x * -1.4426950408889634f)); }
static __device__ __forceinline__ float tanhf_(float x) { return 2.f * rcpf(1.f + ex2f(x * -2.8853900817779268f)) - 1.f; }

static __device__ __forceinline__ uint32_t pack_h2(float a, float b) {
    __half2 h = __floats2half2_rn(a, b);
    return *reinterpret_cast<uint32_t*>(&h);
}
static __device__ __forceinline__ float2 unpack_h2(uint32_t u) {
    __half2 h = *reinterpret_cast<__half2*>(&u);
    return make_float2(__low2float(h), __high2float(h));
}

static __device__ __forceinline__ void ldsm4(uint32_t* r, uint32_t addr) {
    asm volatile("ldmatrix.sync.aligned.m8n8.x4.shared.b16 {%0,%1,%2,%3},[%4];"
                 : "=r"(r[0]), "=r"(r[1]), "=r"(r[2]), "=r"(r[3]) : "r"(addr));
}
static __device__ __forceinline__ void mma16816(float* d, const uint32_t* a, const uint32_t* b) {
    asm volatile("mma.sync.aligned.m16n8k16.row.col.f32.f16.f16.f32 "
                 "{%0,%1,%2,%3},{%4,%5,%6,%7},{%8,%9},{%0,%1,%2,%3};"
                 : "+f"(d[0]), "+f"(d[1]), "+f"(d[2]), "+f"(d[3])
                 : "r"(a[0]), "r"(a[1]), "r"(a[2]), "r"(a[3]), "r"(b[0]), "r"(b[1]));
}

// GEMM for one 128-col gate slab: acc[16][4] += A(16x128, hT rows m0..m0+15) * W_slab^T
// aAddr: per-lane ldmatrix A address (k stride = 32B). bAddr: per-lane W base for this slab.
// W is [n][k] with k contiguous == B col-major -> NON-trans ldmatrix.
static __device__ __forceinline__ void gemm_slab(float acc[16][4], uint32_t aAddr, uint32_t bAddr) {
    #pragma unroll
    for (int k = 0; k < 8; ++k) {
        uint32_t a[4];
        ldsm4(a, aAddr + k * 32);
        #pragma unroll
        for (int np = 0; np < 8; ++np) {
            uint32_t bb[4];
            ldsm4(bb, bAddr + np * (16 * HS * 2) + k * 32);
            mma16816(acc[2 * np],     a, bb);
            mma16816(acc[2 * np + 1], a, bb + 2);
        }
    }
}

// load [384,128] fp32 weight -> fp16 SMEM [384][HS]
static __device__ __forceinline__ void load_w(__half* wT, const float* __restrict__ W, int tid) {
    #pragma unroll
    for (int j = 0; j < 48; ++j) {
        int idx = (tid + j * 256) * 4;
        int g = idx >> 7, k = idx & 127;
        float4 v = *(const float4*)(W + idx);
        __half2* p = (__half2*)&wT[g * HS + k];
        p[0] = __floats2half2_rn(v.x, v.y);
        p[1] = __floats2half2_rn(v.z, v.w);
    }
}

// ===================== Kernel 1: xproj precompute =====================
__global__ void __launch_bounds__(256, 1)
lrnn_pre(const float* __restrict__ x, const float* __restrict__ W_ih,
         const float* __restrict__ b_ih, const float* __restrict__ b_hh) {
    if (blockIdx.x == NCTA) {   // pad rows: pure bias
        for (int i = threadIdx.x; i < BB * 7 * GD; i += 256) {
            int b = i / (7 * GD);
            int rr = i % (7 * GD);
            int p = rr / GD, g = rr % GD;
            g_xproj[(size_t)(b * LP + p) * GD + g] = b_ih[g] + (g < 256 ? b_hh[g] : 0.f);
        }
        return;
    }
    extern __shared__ char smem[];
    __half* xT = (__half*)smem;
    __half* wT = (__half*)(smem + HT_BYTES);
    int tid = threadIdx.x, w = tid >> 5, lane = tid & 31;
    int c = blockIdx.x, b = c >> 4, l0 = (c & 15) << 7;

    load_w(wT, W_ih, tid);
    __syncthreads();

    int m0 = w * 16;
    int g = lane >> 2, tig = lane & 3;
    int rA = m0 + g, rB = rA + 8;

    // warp-private x tile load (rows m0..m0+15)
    {
        int row = m0 + (lane >> 1);
        int cb = (lane & 1) * 64;
        const float* xr = x + (size_t)(b * LL + l0 + row) * DD + cb;
        __half* dst = &xT[row * HS + cb];
        #pragma unroll
        for (int q = 0; q < 16; ++q) {
            float4 v = *(const float4*)(xr + q * 4);
            __half2* p = (__half2*)(dst + q * 4);
            p[0] = __floats2half2_rn(v.x, v.y);
            p[1] = __floats2half2_rn(v.z, v.w);
        }
    }
    __syncwarp();

    uint32_t aAddr = smem_u32(&xT[(m0 + (lane & 15)) * HS + ((lane >> 4) << 3)]);
    int gOff = (lane & 7) + ((lane >> 4) << 3);
    int colOff = ((lane >> 3) & 1) << 3;
    uint32_t wAddr0 = smem_u32(&wT[gOff * HS + colOff]);

    #pragma unroll 1
    for (int s = 0; s < 3; ++s) {
        float acc[16][4];
        #pragma unroll
        for (int j = 0; j < 16; ++j) { acc[j][0] = acc[j][1] = acc[j][2] = acc[j][3] = 0.f; }
        gemm_slab(acc, aAddr, wAddr0 + s * (128 * HS * 2));

        int sc = s * 128;
        float* xoA = g_xproj + ((size_t)(b * LP + 7 + l0 + rA)) * GD + sc;
        float* xoB = xoA + (size_t)8 * GD;
        #pragma unroll
        for (int j = 0; j < 16; ++j) {
            int cc = j * 8 + 2 * tig;
            float2 bi = *(const float2*)(b_ih + sc + cc);
            float bx = 0.f, by = 0.f;
            if (s < 2) { float2 bh = *(const float2*)(b_hh + sc + cc); bx = bh.x; by = bh.y; }
            float2 oA = make_float2(acc[j][0] + bi.x + bx, acc[j][1] + bi.y + by);
            float2 oB = make_float2(acc[j][2] + bi.x + bx, acc[j][3] + bi.y + by);
            *(float2*)(xoA + cc) = oA;
            *(float2*)(xoB + cc) = oB;
        }
    }
}

// ===================== Kernel 2: 8-step local GRU =====================
__global__ void __launch_bounds__(256, 1)
lrnn_main(const float* __restrict__ W_hh, const float* __restrict__ b_hh,
          float* __restrict__ out) {
    extern __shared__ char smem[];
    __half* hT = (__half*)smem;
    __half* wT = (__half*)(smem + HT_BYTES);
    int tid = threadIdx.x, w = tid >> 5, lane = tid & 31;
    int c = blockIdx.x, b = c >> 4, l0 = (c & 15) << 7;

    load_w(wT, W_hh, tid);
    __syncthreads();

    int m0 = w * 16;
    int g = lane >> 2, tig = lane & 3;
    int rA = m0 + g, rB = rA + 8;

    uint32_t aAddr = smem_u32(&hT[(m0 + (lane & 15)) * HS + ((lane >> 4) << 3)]);
    int gOff = (lane & 7) + ((lane >> 4) << 3);
    int colOff = ((lane >> 3) & 1) << 3;
    uint32_t wAddr0 = smem_u32(&wT[gOff * HS + colOff]);

    float h[16][4];
    #pragma unroll
    for (int j = 0; j < 16; ++j) { h[j][0] = h[j][1] = h[j][2] = h[j][3] = 0.f; }
    uint32_t rlo[16], rhi[16], zlo[16], zhi[16];

    const float* xpBase = g_xproj + ((size_t)(b * LP + l0)) * GD;

    #pragma unroll 1
    for (int t = 0; t < KW; ++t) {
        if (t > 0) __syncwarp();   // h SMEM tile rows are warp-private
        const float* xpA = xpBase + (size_t)(rA + t) * GD;
        const float* xpB = xpA + (size_t)8 * GD;

        float acc[16][4];
        // ---- slab r ----
        #pragma unroll
        for (int j = 0; j < 16; ++j) { acc[j][0] = acc[j][1] = acc[j][2] = acc[j][3] = 0.f; }
        if (t > 0) gemm_slab(acc, aAddr, wAddr0);
        #pragma unroll
        for (int j = 0; j < 16; ++j) {
            int cc = j * 8 + 2 * tig;
            float2 xA = *(const float2*)(xpA + cc);
            float2 xB = *(const float2*)(xpB + cc);
            rlo[j] = pack_h2(sigf(acc[j][0] + xA.x), sigf(acc[j][1] + xA.y));
            rhi[j] = pack_h2(sigf(acc[j][2] + xB.x), sigf(acc[j][3] + xB.y));
        }
        // ---- slab z ----
        #pragma unroll
        for (int j = 0; j < 16; ++j) { acc[j][0] = acc[j][1] = acc[j][2] = acc[j][3] = 0.f; }
        if (t > 0) gemm_slab(acc, aAddr, wAddr0 + 128 * HS * 2);
        #pragma unroll
        for (int j = 0; j < 16; ++j) {
            int cc = j * 8 + 2 * tig;
            float2 xA = *(const float2*)(xpA + 128 + cc);
            float2 xB = *(const float2*)(xpB + 128 + cc);
            zlo[j] = pack_h2(sigf(acc[j][0] + xA.x), sigf(acc[j][1] + xA.y));
            zhi[j] = pack_h2(sigf(acc[j][2] + xB.x), sigf(acc[j][3] + xB.y));
        }
        // ---- slab n + state update ----
        #pragma unroll
        for (int j = 0; j < 16; ++j) { acc[j][0] = acc[j][1] = acc[j][2] = acc[j][3] = 0.f; }
        if (t > 0) gemm_slab(acc, aAddr, wAddr0 + 256 * HS * 2);
        #pragma unroll
        for (int j = 0; j < 16; ++j) {
            int cc = j * 8 + 2 * tig;
            float2 xA = *(const float2*)(xpA + 256 + cc);
            float2 xB = *(const float2*)(xpB + 256 + cc);
            float2 bh = *(const float2*)(b_hh + 256 + cc);
            float2 r01 = unpack_h2(rlo[j]), r23 = unpack_h2(rhi[j]);
            float2 z01 = unpack_h2(zlo[j]), z23 = unpack_h2(zhi[j]);
            float n0 = tanhf_(fmaf(r01.x, acc[j][0] + bh.x, xA.x));
            float n1 = tanhf_(fmaf(r01.y, acc[j][1] + bh.y, xA.y));
            float n2 = tanhf_(fmaf(r23.x, acc[j][2] + bh.x, xB.x));
            float n3 = tanhf_(fmaf(r23.y, acc[j][3] + bh.y, xB.y));
            h[j][0] = n0 + z01.x * (h[j][0] - n0);
            h[j][1] = n1 + z01.y * (h[j][1] - n1);
            h[j][2] = n2 + z23.x * (h[j][2] - n2);
            h[j][3] = n3 + z23.y * (h[j][3] - n3);
            // fp16 copy into SMEM for next step's MMA A operand
            *(uint32_t*)&hT[rA * HS + cc] = pack_h2(h[j][0], h[j][1]);
            *(uint32_t*)&hT[rB * HS + cc] = pack_h2(h[j][2], h[j][3]);
        }
    }

    // final hidden state -> out (fp32)
    float* oA = out + (size_t)(b * LL + l0 + rA) * DD;
    float* oB = oA + (size_t)8 * DD;
    #pragma unroll
    for (int j = 0; j < 16; ++j) {
        int cc = j * 8 + 2 * tig;
        *(float2*)(oA + cc) = make_float2(h[j][0], h[j][1]);
        *(float2*)(oB + cc) = make_float2(h[j][2], h[j][3]);
    }
}

// ===================== launch =====================
extern "C" void kernel_launch(void* const* d_in, const int* in_sizes, int n_in,
                              void* d_out, int out_size) {
    const float* x    = (const float*)d_in[0];
    const float* W_ih = (const float*)d_in[1];
    const float* W_hh = (const float*)d_in[2];
    const float* b_ih = (const float*)d_in[3];
    const float* b_hh = (const float*)d_in[4];
    float* out = (float*)d_out;

    cudaFuncSetAttribute(lrnn_pre,  cudaFuncAttributeMaxDynamicSharedMemorySize, SMEM_BYTES);
    cudaFuncSetAttribute(lrnn_main, cudaFuncAttributeMaxDynamicSharedMemorySize, SMEM_BYTES);

    lrnn_pre<<<NCTA + 1, 256, SMEM_BYTES>>>(x, W_ih, b_ih, b_hh);
    lrnn_main<<<NCTA, 256, SMEM_BYTES>>>(W_hh, b_hh, out);
}